// round 17
// baseline (speedup 1.0000x reference)
#include <cuda_runtime.h>

#define NBATCH 2048
#define NTOT   6561          // 3^8
#define NQUAD  1640          // full 4-group (144B) quads; group 6560 is the tail
#define GBLK   32            // k1 blocks
#define TBLK   256           // 32*256 = 8192 threads; 4 threads per batch element
#define GBLK2  8             // k2 blocks (8*256 = 2048 = one thread per element)
#define TBLK2  256
#define ASTRIDE 128          // s64 stride (1KB) -> accumulators hit distinct LTS

#define SCALE_F 1099511627776.0f       // 2^40  (exact in fp32)
#define INV_SF  9.094947017729282e-13f // 2^-40 (exact in fp32)

__device__ long long g_acc[10 * ASTRIDE]; // [k*ASTRIDE]: C buckets 0..8, S at k=9
__device__ int g_ctr2;                    // epoch-reset ticket (monotonic)

__device__ __forceinline__ float rcpa(float v) {
    float r; asm("rcp.approx.f32 %0, %1;" : "=f"(r) : "f"(v)); return r;
}
__device__ __forceinline__ float lg2a(float v) {
    float r; asm("lg2.approx.f32 %0, %1;" : "=f"(r) : "f"(v)); return r;
}
__device__ __forceinline__ float ex2a(float v) {
    float r; asm("ex2.approx.f32 %0, %1;" : "=f"(r) : "f"(v)); return r;
}
__device__ __forceinline__ void red_s64(long long* p, float v) {
    long long q = (long long)(v * SCALE_F);
    asm volatile("red.relaxed.gpu.global.add.u64 [%0], %1;" :: "l"(p), "l"(q) : "memory");
}

// K-form: (1+t), t = ex2(b*lg2((x-c)^2) - K), K = b*lg2(a^2). numpy edge cases:
//   b==0 -> t=1 (guard); x2==0,b>0 -> t=0 (auto); a==0,b>0 -> t=inf (auto, P->0)
__device__ __forceinline__ float one_plus_t_K(float x, float b, float c, float K) {
    float d  = x - c;
    float x2 = d * d;
    float t  = ex2a(fmaf(b, lg2a(x2), -K));
    if (b == 0.0f) t = 1.0f;
    return 1.0f + t;
}
// Direct form (k2): t = ((x-c)*rcp(a))^2 ^ b, same edge cases explicit.
__device__ __forceinline__ float one_plus_t_D(float x, float a, float b, float c) {
    float u  = (x - c) * rcpa(a);
    float x2 = u * u;
    float t;
    if (b == 0.0f)       t = 1.0f;
    else if (x2 == 0.0f) t = 0.0f;
    else                 t = ex2a(b * lg2a(x2));
    return 1.0f + t;
}

// ================= k1: reduce (C buckets + global S) =================
__global__ __launch_bounds__(TBLK)
void anfis_reduce(const float* __restrict__ inp,
                  const float* __restrict__ prem,
                  const float* __restrict__ conseq) {
    // Allow the dependent kernel to launch immediately (PDL overlap).
    asm volatile("griddepcontrol.launch_dependents;" ::: "memory");

    __shared__ float swC[8][9];
    __shared__ float swS[8];

    const int tid  = threadIdx.x;
    const int bi   = blockIdx.x;
    const int w    = tid >> 5, lane = tid & 31;
    const int quarter = lane >> 3;                 // var pair (0..3)
    const int j    = lane & 7;
    const int b    = bi * 64 + w * 8 + j;          // batch element

    // Conseq quads on lanes 24..31 of every warp, warp-interleaved for balance.
    float4 cv[9];
    const int qidx = (lane - 24) * 8 + w;          // 0..63 for lanes 24..31
    const int q    = bi + GBLK * qidx;
    const bool qact = (lane >= 24) && (q < NQUAD);
    if (qact) {
        const float4* p = (const float4*)(conseq + 36 * q);
#pragma unroll
        for (int m = 0; m < 9; m++) cv[m] = __ldg(p + m);
    }

    // Tail group 6560: block 0 / warp 0 / lanes 24..31, folded pre-butterfly.
    float tail_v = 0.0f, tail_8 = 0.0f;
    if (bi == 0 && w == 0 && lane >= 24) {
        tail_v = __ldg(conseq + 36 * NQUAD + (lane - 24));
        if (lane == 24) tail_8 = __ldg(conseq + 36 * NQUAD + 8);
    }

    const int i0 = 2 * quarter;
    const float x0 = __ldg(inp + i0 * NBATCH + b);
    const float x1 = __ldg(inp + (i0 + 1) * NBATCH + b);

    const float2* pr = (const float2*)(prem + 18 * quarter);
    float pp[18];
#pragma unroll
    for (int m = 0; m < 9; m++) {
        float2 v = __ldg(pr + m);
        pp[2 * m] = v.x; pp[2 * m + 1] = v.y;
    }

    // K constants: lane j<6 of each group computes K_j = b_j*lg2(a_j^2)
    float Kv = 0.0f;
    if (j < 6) {
        const float aj = __ldg(prem + 18 * quarter + 3 * j);
        const float bj = __ldg(prem + 18 * quarter + 3 * j + 1);
        Kv = bj * 2.0f * lg2a(fabsf(aj));
    }
    const int gb = lane & 24;
    const float K0 = __shfl_sync(0xffffffffu, Kv, gb + 0);
    const float K1 = __shfl_sync(0xffffffffu, Kv, gb + 1);
    const float K2 = __shfl_sync(0xffffffffu, Kv, gb + 2);
    const float K3 = __shfl_sync(0xffffffffu, Kv, gb + 3);
    const float K4 = __shfl_sync(0xffffffffu, Kv, gb + 4);
    const float K5 = __shfl_sync(0xffffffffu, Kv, gb + 5);

    float q0 = one_plus_t_K(x0, pp[1],  pp[2],  K0) * one_plus_t_K(x1, pp[10], pp[11], K3);
    float q1 = one_plus_t_K(x0, pp[4],  pp[5],  K1) * one_plus_t_K(x1, pp[13], pp[14], K4);
    float q2 = one_plus_t_K(x0, pp[7],  pp[8],  K2) * one_plus_t_K(x1, pp[16], pp[17], K5);

    // combine the 4 quarter-lanes (lane bits 3,4)
    q0 *= __shfl_xor_sync(0xffffffffu, q0, 8);
    q1 *= __shfl_xor_sync(0xffffffffu, q1, 8);
    q2 *= __shfl_xor_sync(0xffffffffu, q2, 8);
    q0 *= __shfl_xor_sync(0xffffffffu, q0, 16);
    q1 *= __shfl_xor_sync(0xffffffffu, q1, 16);
    q2 *= __shfl_xor_sync(0xffffffffu, q2, 16);
    float S = rcpa(q0) + rcpa(q1) + rcpa(q2);

    // warp S sum over the 8 distinct elements (lane bits 0..2 only)
    S += __shfl_xor_sync(0xffffffffu, S, 1);
    S += __shfl_xor_sync(0xffffffffu, S, 2);
    S += __shfl_xor_sync(0xffffffffu, S, 4);

    // Conseq buckets
    float acc[9];
#pragma unroll
    for (int v = 0; v < 9; v++) acc[v] = 0.0f;
    if (qact) {
#pragma unroll
        for (int m = 0; m < 9; m++) {
            acc[(4 * m + 0) % 9] += cv[m].x;
            acc[(4 * m + 1) % 9] += cv[m].y;
            acc[(4 * m + 2) % 9] += cv[m].z;
            acc[(4 * m + 3) % 9] += cv[m].w;
        }
    }
    if (bi == 0 && w == 0 && lane >= 24) {
        acc[lane - 24] += tail_v;
        if (lane == 24) acc[8] += tail_8;
    }
    // butterfly over lanes 24..31 (bits 0..2; inactive lanes hold zeros)
#pragma unroll
    for (int v = 0; v < 9; v++) {
        acc[v] += __shfl_xor_sync(0xffffffffu, acc[v], 1);
        acc[v] += __shfl_xor_sync(0xffffffffu, acc[v], 2);
        acc[v] += __shfl_xor_sync(0xffffffffu, acc[v], 4);
    }
    if (lane >= 24) swC[w][lane - 24] = acc[lane - 24];
    if (lane == 24) swC[w][8] = acc[8];
    if (lane == 0)  swS[w] = S;
    __syncthreads();

    // Publish: deterministic s64 fixed-point reds (one set per block).
    if (tid < 9) {
        float s = ((swC[0][tid] + swC[1][tid]) + (swC[2][tid] + swC[3][tid]))
                + ((swC[4][tid] + swC[5][tid]) + (swC[6][tid] + swC[7][tid]));
        red_s64(&g_acc[tid * ASTRIDE], s);
    }
    if (tid == 9) {
        float s = ((swS[0] + swS[1]) + (swS[2] + swS[3]))
                + ((swS[4] + swS[5]) + (swS[6] + swS[7]));
        red_s64(&g_acc[9 * ASTRIDE], s);
    }
}

// ================= k2: finalize (PDL-overlapped) =================
__global__ __launch_bounds__(TBLK2)
void anfis_final(const float* __restrict__ inp,
                 const float* __restrict__ prem,
                 float* __restrict__ out) {
    const int tid = threadIdx.x;
    const int b   = blockIdx.x * TBLK2 + tid;      // one element per thread

    // --- Pre-sync work: fully overlapped with k1 ---
    float x[8];
#pragma unroll
    for (int i = 0; i < 8; i++) x[i] = __ldg(inp + i * NBATCH + b);

    float q0 = 1.0f;
#pragma unroll
    for (int i = 0; i < 8; i++) {
        const float* r = prem + 9 * i;             // set-0 row of variable i
        q0 *= one_plus_t_D(x[i], __ldg(r), __ldg(r + 1), __ldg(r + 2));
    }
    const float P0 = rcpa(q0);

    // --- Wait for k1 completion (HW grid dependency, memory flushed) ---
    asm volatile("griddepcontrol.wait;" ::: "memory");

    float C[9];
#pragma unroll
    for (int v = 0; v < 9; v++)
        C[v] = (float)__ldcg(&g_acc[v * ASTRIDE]) * INV_SF;
    const float St = (float)__ldcg(&g_acc[9 * ASTRIDE]) * INV_SF;

    float dot = C[8];                              // bias
#pragma unroll
    for (int i = 0; i < 8; i++) dot = fmaf(x[i], C[i], dot);
    out[b] = P0 * dot * rcpa(2187.0f * St);        // Z = 2187 * sum_b(P0+P1+P2)

    // --- Epoch reset: last-ticket block zeroes accumulators for next launch.
    __syncthreads();                               // all reads in block done
    if (tid == 0) {
        int old;
        asm volatile("atom.release.gpu.global.add.u32 %0, [%1], %2;"
                     : "=r"(old) : "l"(&g_ctr2), "r"(1) : "memory");
        if ((old & (GBLK2 - 1)) == GBLK2 - 1) {    // last block of this epoch
#pragma unroll
            for (int k = 0; k < 10; k++) g_acc[k * ASTRIDE] = 0;
        }
    }
}

extern "C" void kernel_launch(void* const* d_in, const int* in_sizes, int n_in,
                              void* d_out, int out_size) {
    const float* inp    = (const float*)d_in[0];   // (8, 2048)
    const float* prem   = (const float*)d_in[1];   // (24, 3)
    const float* conseq = (const float*)d_in[2];   // (59049, 1)
    float* out = (float*)d_out;                    // (2048, 1)

    anfis_reduce<<<GBLK, TBLK>>>(inp, prem, conseq);

    cudaLaunchConfig_t cfg = {};
    cfg.gridDim  = dim3(GBLK2, 1, 1);
    cfg.blockDim = dim3(TBLK2, 1, 1);
    cfg.dynamicSmemBytes = 0;
    cfg.stream = 0;                                // same (default) stream
    cudaLaunchAttribute attr[1];
    attr[0].id = cudaLaunchAttributeProgrammaticStreamSerialization;
    attr[0].val.programmaticStreamSerializationAllowed = 1;
    cfg.attrs = attr;
    cfg.numAttrs = 1;
    cudaLaunchKernelEx(&cfg, anfis_final, inp, prem, out);
}